// round 15
// baseline (speedup 1.0000x reference)
#include <cuda_runtime.h>
#include <cuda_bf16.h>
#include <math.h>
#include <stdint.h>

#define B_    8
#define C_    192
#define Nn    3136
#define Kn    9
#define C2_   384
#define OUT_  192
#define M_    25088
#define KSPLIT 768          // [hi(384) | lo(384)] bf16 columns
#define KCHUNKS 18          // 3 passes x 6 chunks of 64
#define EPS_  1e-5f

// ---------------- scratch ----------------
__device__ __align__(128) float g_xt[(size_t)M_ * C_];
__device__ __align__(256) __nv_bfloat16 gA1[(size_t)M_ * KSPLIT];
__device__ __align__(256) __nv_bfloat16 gA2[(size_t)M_ * KSPLIT];
__device__ __align__(256) __nv_bfloat16 gW1[(size_t)C2_ * KSPLIT];
__device__ __align__(256) __nv_bfloat16 gW2[(size_t)OUT_ * KSPLIT];
__device__ __align__(128) float g_h1[(size_t)M_ * C2_];
__device__ __align__(128) float g_h2[(size_t)M_ * OUT_];
__device__ float g_sum1[C2_], g_sq1[C2_], g_sum2[OUT_], g_sq2[OUT_];
__device__ float g_scale1[C2_], g_shift1[C2_], g_scale2[OUT_], g_shift2[OUT_];

// ---------------- helpers ----------------
__device__ __forceinline__ uint32_t smem_u32(const void* p) {
    uint32_t a;
    asm("{ .reg .u64 t; cvta.to.shared.u64 t, %1; cvt.u32.u64 %0, t; }" : "=r"(a) : "l"(p));
    return a;
}
#define CP16(dst, src) asm volatile("cp.async.cg.shared.global [%0], [%1], 16;" :: "r"(dst), "l"(src) : "memory")
#define CP_COMMIT()    asm volatile("cp.async.commit_group;" ::: "memory")

__device__ __forceinline__ void ldm_x4(uint32_t* r, uint32_t addr) {
    asm volatile("ldmatrix.sync.aligned.m8n8.x4.shared.b16 {%0,%1,%2,%3}, [%4];"
                 : "=r"(r[0]), "=r"(r[1]), "=r"(r[2]), "=r"(r[3]) : "r"(addr));
}
__device__ __forceinline__ void mma16816(float* c, const uint32_t* a, const uint32_t* b) {
    asm volatile("mma.sync.aligned.m16n8k16.row.col.f32.bf16.bf16.f32 "
                 "{%0,%1,%2,%3}, {%4,%5,%6,%7}, {%8,%9}, {%0,%1,%2,%3};"
                 : "+f"(c[0]), "+f"(c[1]), "+f"(c[2]), "+f"(c[3])
                 : "r"(a[0]), "r"(a[1]), "r"(a[2]), "r"(a[3]), "r"(b[0]), "r"(b[1]));
}
__device__ __forceinline__ float gelu_f(float x) {
    return 0.5f * x * (1.0f + erff(x * 0.7071067811865475f));
}

// ---------------- small kernels ----------------
__global__ void k_transpose(const float* __restrict__ x) {
    __shared__ float tile[32][33];
    int b = blockIdx.z, n0 = blockIdx.x * 32, c0 = blockIdx.y * 32;
    int tx = threadIdx.x, ty = threadIdx.y;
    const float* xb = x + (size_t)b * C_ * Nn;
#pragma unroll
    for (int i = 0; i < 4; i++)
        tile[ty + i * 8][tx] = xb[(size_t)(c0 + ty + i * 8) * Nn + n0 + tx];
    __syncthreads();
    float* xtb = g_xt + (size_t)b * Nn * C_;
#pragma unroll
    for (int i = 0; i < 4; i++)
        xtb[(size_t)(n0 + ty + i * 8) * C_ + c0 + tx] = tile[tx][ty + i * 8];
}

// gather + neighbor-diff max; interleaved channels, hi/lo bf16 split -> gA1 [M,768]
__global__ void k_feats(const int* __restrict__ edge) {
    __shared__ int sj[Kn], si[Kn];
    int n = blockIdx.x, b = blockIdx.y;
    int t = threadIdx.x;
    if (t < Kn)          sj[t]      = edge[((size_t)b * Nn + n) * Kn + t];
    else if (t < 2 * Kn) si[t - Kn] = edge[((size_t)(B_ + b) * Nn + n) * Kn + (t - Kn)];
    __syncthreads();
    const float* xb = g_xt + (size_t)b * Nn * C_;
    int c = t;
    float xv = xb[(size_t)n * C_ + c];
    float mx = -INFINITY;
#pragma unroll
    for (int k = 0; k < Kn; k++)
        mx = fmaxf(mx, xb[(size_t)sj[k] * C_ + c] - xb[(size_t)si[k] * C_ + c]);
    __nv_bfloat16* row = gA1 + (size_t)(b * Nn + n) * KSPLIT;
    __nv_bfloat16 xh = __float2bfloat16(xv);
    __nv_bfloat16 mh = __float2bfloat16(mx);
    row[2 * c]           = xh;
    row[2 * c + 1]       = mh;
    row[384 + 2 * c]     = __float2bfloat16(xv - __bfloat162float(xh));
    row[384 + 2 * c + 1] = __float2bfloat16(mx - __bfloat162float(mh));
}

// fp32 weights -> bf16 hi/lo split; also zeros stat accumulators
__global__ void k_wprep(const float* __restrict__ w1, const float* __restrict__ w2) {
    int i = blockIdx.x * 256 + threadIdx.x;
    if (i < C2_)  { g_sum1[i] = 0.f; g_sq1[i] = 0.f; }
    if (i < OUT_) { g_sum2[i] = 0.f; g_sq2[i] = 0.f; }
    if (i < C2_ * C2_) {
        int r = i / C2_, c = i % C2_;
        float v = w1[i];
        __nv_bfloat16 h = __float2bfloat16(v);
        gW1[(size_t)r * KSPLIT + c]       = h;
        gW1[(size_t)r * KSPLIT + 384 + c] = __float2bfloat16(v - __bfloat162float(h));
    } else if (i < C2_ * C2_ + OUT_ * C2_) {
        int j = i - C2_ * C2_;
        int r = j / C2_, c = j % C2_;
        float v = w2[j];
        __nv_bfloat16 h = __float2bfloat16(v);
        gW2[(size_t)r * KSPLIT + c]       = h;
        gW2[(size_t)r * KSPLIT + 384 + c] = __float2bfloat16(v - __bfloat162float(h));
    }
}

// ---------------- bf16 mma.sync GEMM with fused bias + BN stats ----------------
// BM=64, BK=64, 3-stage cp.async pipeline, 8 warps (2m x 4n), warp tile 32 x (BN/4).
// __launch_bounds__(256, 3): cap regs so 3 CTAs (24 warps) fit per SM.
// acc is only MFRAG(2) x NFRAG x 4 regs, so the cap is sufficient without spill.
#define BMg 64
#define MFRAG 2
#define STG 3

template <int BN>
__global__ void __launch_bounds__(256, 3) k_gemm_mma(
    const __nv_bfloat16* __restrict__ A, const __nv_bfloat16* __restrict__ W,
    const float* __restrict__ bias, float* __restrict__ Cout,
    float* __restrict__ sOut, float* __restrict__ qOut, int Nout)
{
    constexpr int WN = BN / 4;          // warp n-extent
    constexpr int NFRAG = WN / 8;       // n8 frags per warp
    constexpr int A_BYTES = BMg * 128;  // 64 rows x 64 bf16 = 8 KB
    constexpr int B_BYTES = BN * 128;
    constexpr int STAGE = A_BYTES + B_BYTES;

    extern __shared__ char sm[];
    __shared__ float redS[BN], redQ[BN];
    uint32_t sb = smem_u32(sm);

    int tid = threadIdx.x, lane = tid & 31, wid = tid >> 5;
    int wm = wid & 1, wn = wid >> 1;          // warps: 2 (m) x 4 (n)
    int mBase = blockIdx.y * BMg, nBase = blockIdx.x * BN;

    for (int j = tid; j < BN; j += 256) { redS[j] = 0.f; redQ[j] = 0.f; }

    float acc[MFRAG][NFRAG][4];
#pragma unroll
    for (int mi = 0; mi < MFRAG; mi++)
#pragma unroll
        for (int nf = 0; nf < NFRAG; nf++)
#pragma unroll
            for (int q = 0; q < 4; q++) acc[mi][nf][q] = 0.f;

    auto load_stage = [&](int t, int s) {
        int u = t % 6;
        int kA = (t < 6 || t >= 12) ? u * 64 : 384 + u * 64;
        int kW = (t < 12) ? u * 64 : 384 + u * 64;
        const char* Ag = (const char*)A + ((size_t)mBase * KSPLIT + kA) * 2;
        const char* Wg = (const char*)W + ((size_t)nBase * KSPLIT + kW) * 2;
        uint32_t as = sb + s * STAGE;
        uint32_t bs = as + A_BYTES;
#pragma unroll
        for (int i = 0; i < BMg * 8 / 256; i++) {      // A granules (512/256 = 2)
            int gi = tid + i * 256;
            int r = gi >> 3, g = gi & 7;
            CP16(as + r * 128 + ((g ^ (r & 7)) << 4), Ag + (size_t)r * (KSPLIT * 2) + g * 16);
        }
#pragma unroll
        for (int i = 0; i < BN * 8 / 256; i++) {       // W granules
            int gi = tid + i * 256;
            int n = gi >> 3, g = gi & 7;
            CP16(bs + n * 128 + ((g ^ (n & 7)) << 4), Wg + (size_t)n * (KSPLIT * 2) + g * 16);
        }
        CP_COMMIT();
    };

    for (int t = 0; t < STG - 1; t++) load_stage(t, t);

    for (int t = 0; t < KCHUNKS; t++) {
        if (t + 1 < KCHUNKS) asm volatile("cp.async.wait_group 1;" ::: "memory");
        else                 asm volatile("cp.async.wait_group 0;" ::: "memory");
        __syncthreads();
        if (t + STG - 1 < KCHUNKS) load_stage(t + STG - 1, (t + STG - 1) % STG);

        uint32_t as = sb + (t % STG) * STAGE;
        uint32_t bsm = as + A_BYTES;
#pragma unroll
        for (int ks = 0; ks < 4; ks++) {
            uint32_t af[MFRAG][4];
#pragma unroll
            for (int mi = 0; mi < MFRAG; mi++) {
                int row = wm * 32 + mi * 16 + (lane & 15);
                int g = ks * 2 + (lane >> 4);
                ldm_x4(af[mi], as + row * 128 + ((g ^ (row & 7)) << 4));
            }
            uint32_t bf[NFRAG][2];
#pragma unroll
            for (int j2 = 0; j2 < NFRAG / 2; j2++) {
                int quad = lane >> 3;
                int n = wn * WN + j2 * 16 + (lane & 7) + (quad >> 1) * 8;
                int g = ks * 2 + (quad & 1);
                uint32_t r4[4];
                ldm_x4(r4, bsm + n * 128 + ((g ^ (n & 7)) << 4));
                bf[2 * j2][0] = r4[0]; bf[2 * j2][1] = r4[1];
                bf[2 * j2 + 1][0] = r4[2]; bf[2 * j2 + 1][1] = r4[3];
            }
#pragma unroll
            for (int mi = 0; mi < MFRAG; mi++)
#pragma unroll
                for (int nf = 0; nf < NFRAG; nf++)
                    mma16816(acc[mi][nf], af[mi], bf[nf]);
        }
    }

    // -------- epilogue: bias, store, fused per-channel sum/sumsq --------
    int g = lane >> 2, tig = lane & 3;
#pragma unroll
    for (int nf = 0; nf < NFRAG; nf++) {
        int colL = wn * WN + nf * 8 + 2 * tig;        // block-local column
        int col = nBase + colL;
        float b0 = bias[col], b1 = bias[col + 1];
        float s0 = 0.f, q0 = 0.f, s1 = 0.f, q1 = 0.f;
#pragma unroll
        for (int mi = 0; mi < MFRAG; mi++) {
            int row0 = mBase + wm * 32 + mi * 16 + g;
            float v0 = acc[mi][nf][0] + b0;
            float v1 = acc[mi][nf][1] + b1;
            float v2 = acc[mi][nf][2] + b0;
            float v3 = acc[mi][nf][3] + b1;
            *(float2*)(Cout + (size_t)row0 * Nout + col)       = make_float2(v0, v1);
            *(float2*)(Cout + (size_t)(row0 + 8) * Nout + col) = make_float2(v2, v3);
            s0 += v0 + v2; q0 += v0 * v0 + v2 * v2;
            s1 += v1 + v3; q1 += v1 * v1 + v3 * v3;
        }
#pragma unroll
        for (int o = 4; o <= 16; o <<= 1) {           // reduce over g (lane bits 2..4)
            s0 += __shfl_xor_sync(0xffffffffu, s0, o);
            q0 += __shfl_xor_sync(0xffffffffu, q0, o);
            s1 += __shfl_xor_sync(0xffffffffu, s1, o);
            q1 += __shfl_xor_sync(0xffffffffu, q1, o);
        }
        if (g == 0) {
            atomicAdd(&redS[colL], s0);     atomicAdd(&redQ[colL], q0);
            atomicAdd(&redS[colL + 1], s1); atomicAdd(&redQ[colL + 1], q1);
        }
    }
    __syncthreads();
    if (tid < BN) {
        atomicAdd(&sOut[nBase + tid], redS[tid]);
        atomicAdd(&qOut[nBase + tid], redQ[tid]);
    }
}

// ---------------- stats -> scale/shift ----------------
__global__ void k_fin(const float* __restrict__ sum, const float* __restrict__ sq,
                      const float* __restrict__ g, const float* __restrict__ beta,
                      float* __restrict__ scale, float* __restrict__ shift, int Cn)
{
    int c = threadIdx.x;
    if (c < Cn) {
        float mean = sum[c] * (1.0f / M_);
        float var  = sq[c] * (1.0f / M_) - mean * mean;
        float sc = g[c] * rsqrtf(var + EPS_);
        scale[c] = sc;
        shift[c] = beta[c] - mean * sc;
    }
}

// ---------------- BN1+GELU1, fp32 h1 -> bf16 hi/lo gA2 ----------------
__global__ void k_act() {
    int i = blockIdx.x * blockDim.x + threadIdx.x;   // float4 index over [M,384]
    float4 v = ((const float4*)g_h1)[i];
    int c = (i % 96) * 4;
    int m = i / 96;
    float o[4];
    o[0] = gelu_f(g_scale1[c + 0] * v.x + g_shift1[c + 0]);
    o[1] = gelu_f(g_scale1[c + 1] * v.y + g_shift1[c + 1]);
    o[2] = gelu_f(g_scale1[c + 2] * v.z + g_shift1[c + 2]);
    o[3] = gelu_f(g_scale1[c + 3] * v.w + g_shift1[c + 3]);
    __nv_bfloat16 h[4], l[4];
#pragma unroll
    for (int q = 0; q < 4; q++) {
        h[q] = __float2bfloat16(o[q]);
        l[q] = __float2bfloat16(o[q] - __bfloat162float(h[q]));
    }
    __nv_bfloat16* rowp = gA2 + (size_t)m * KSPLIT + c;
    *(__nv_bfloat162*)(rowp)           = *(__nv_bfloat162*)&h[0];
    *(__nv_bfloat162*)(rowp + 2)       = *(__nv_bfloat162*)&h[2];
    *(__nv_bfloat162*)(rowp + 384)     = *(__nv_bfloat162*)&l[0];
    *(__nv_bfloat162*)(rowp + 384 + 2) = *(__nv_bfloat162*)&l[2];
}

// ---------------- BN2+GELU2 + transpose -> NCHW ----------------
__global__ void k_out(float* __restrict__ out) {
    __shared__ float tile[32][33];
    int b = blockIdx.z, n0 = blockIdx.x * 32, o0 = blockIdx.y * 32;
    int tx = threadIdx.x, ty = threadIdx.y;
    const float* h2 = g_h2 + (size_t)b * Nn * OUT_;
#pragma unroll
    for (int i = 0; i < 4; i++) {
        int n = n0 + ty + i * 8;
        int o = o0 + tx;
        float v = h2[(size_t)n * OUT_ + o];
        tile[ty + i * 8][tx] = gelu_f(g_scale2[o] * v + g_shift2[o]);
    }
    __syncthreads();
    float* ob = out + (size_t)b * OUT_ * Nn;
#pragma unroll
    for (int i = 0; i < 4; i++)
        ob[(size_t)(o0 + ty + i * 8) * Nn + n0 + tx] = tile[tx][ty + i * 8];
}

// ---------------- launch ----------------
extern "C" void kernel_launch(void* const* d_in, const int* in_sizes, int n_in,
                              void* d_out, int out_size) {
    const float* x     = (const float*)d_in[0];
    const int*   edge  = (const int*)d_in[1];
    const float* w1    = (const float*)d_in[2];
    const float* b1    = (const float*)d_in[3];
    const float* g1    = (const float*)d_in[4];
    const float* beta1 = (const float*)d_in[5];
    const float* w2    = (const float*)d_in[6];
    const float* b2    = (const float*)d_in[7];
    const float* g2    = (const float*)d_in[8];
    const float* beta2 = (const float*)d_in[9];
    float* out = (float*)d_out;

    __nv_bfloat16 *pA1, *pA2, *pW1, *pW2;
    float *pH1, *pH2, *pS1, *pQ1, *pS2, *pQ2, *pSc1, *pSh1, *pSc2, *pSh2;
    cudaGetSymbolAddress((void**)&pA1, gA1);
    cudaGetSymbolAddress((void**)&pA2, gA2);
    cudaGetSymbolAddress((void**)&pW1, gW1);
    cudaGetSymbolAddress((void**)&pW2, gW2);
    cudaGetSymbolAddress((void**)&pH1, g_h1);
    cudaGetSymbolAddress((void**)&pH2, g_h2);
    cudaGetSymbolAddress((void**)&pS1, g_sum1);
    cudaGetSymbolAddress((void**)&pQ1, g_sq1);
    cudaGetSymbolAddress((void**)&pS2, g_sum2);
    cudaGetSymbolAddress((void**)&pQ2, g_sq2);
    cudaGetSymbolAddress((void**)&pSc1, g_scale1);
    cudaGetSymbolAddress((void**)&pSh1, g_shift1);
    cudaGetSymbolAddress((void**)&pSc2, g_scale2);
    cudaGetSymbolAddress((void**)&pSh2, g_shift2);

    const int SM1 = STG * (BMg * 128 + 128 * 128);   // 72 KB -> 3 CTAs/SM
    const int SM2 = STG * (BMg * 128 + 64 * 128);    // 48 KB -> 3 CTAs/SM
    cudaFuncSetAttribute(k_gemm_mma<128>, cudaFuncAttributeMaxDynamicSharedMemorySize, SM1);
    cudaFuncSetAttribute(k_gemm_mma<64>,  cudaFuncAttributeMaxDynamicSharedMemorySize, SM2);

    k_transpose<<<dim3(Nn / 32, C_ / 32, B_), dim3(32, 8)>>>(x);
    k_feats<<<dim3(Nn, B_), C_>>>(edge);
    k_wprep<<<(C2_ * C2_ + OUT_ * C2_ + 255) / 256, 256>>>(w1, w2);

    k_gemm_mma<128><<<dim3(C2_ / 128, M_ / BMg), 256, SM1>>>(pA1, pW1, b1, pH1, pS1, pQ1, C2_);
    k_fin<<<1, C2_>>>(pS1, pQ1, g1, beta1, pSc1, pSh1, C2_);
    k_act<<<(M_ * C2_ / 4) / 256, 256>>>();

    k_gemm_mma<64><<<dim3(OUT_ / 64, M_ / BMg), 256, SM2>>>(pA2, pW2, b2, pH2, pS2, pQ2, OUT_);
    k_fin<<<1, OUT_>>>(pS2, pQ2, g2, beta2, pSc2, pSh2, OUT_);

    k_out<<<dim3(Nn / 32, OUT_ / 32, B_), dim3(32, 8)>>>(out);
}

// round 16
// speedup vs baseline: 1.5882x; 1.5882x over previous
#include <cuda_runtime.h>
#include <cuda_bf16.h>
#include <math.h>
#include <stdint.h>

#define B_    8
#define C_    192
#define Nn    3136
#define Kn    9
#define C2_   384
#define OUT_  192
#define M_    25088
#define KSPLIT 768          // [hi(384) | lo(384)] bf16 columns
#define KCHUNKS 18          // 3 passes x 6 chunks of 64
#define EPS_  1e-5f

// ---------------- scratch ----------------
__device__ __align__(128) float g_xt[(size_t)M_ * C_];
__device__ __align__(256) __nv_bfloat16 gA1[(size_t)M_ * KSPLIT];
__device__ __align__(256) __nv_bfloat16 gA2[(size_t)M_ * KSPLIT];
__device__ __align__(256) __nv_bfloat16 gW1[(size_t)C2_ * KSPLIT];
__device__ __align__(256) __nv_bfloat16 gW2[(size_t)OUT_ * KSPLIT];
__device__ __align__(128) float g_h1[(size_t)M_ * C2_];
__device__ __align__(128) float g_h2[(size_t)M_ * OUT_];
__device__ float g_sum1[C2_], g_sq1[C2_], g_sum2[OUT_], g_sq2[OUT_];
__device__ float g_scale1[C2_], g_shift1[C2_], g_scale2[OUT_], g_shift2[OUT_];

// ---------------- helpers ----------------
__device__ __forceinline__ uint32_t smem_u32(const void* p) {
    uint32_t a;
    asm("{ .reg .u64 t; cvta.to.shared.u64 t, %1; cvt.u32.u64 %0, t; }" : "=r"(a) : "l"(p));
    return a;
}
#define CP16(dst, src) asm volatile("cp.async.cg.shared.global [%0], [%1], 16;" :: "r"(dst), "l"(src) : "memory")
#define CP_COMMIT()    asm volatile("cp.async.commit_group;" ::: "memory")

__device__ __forceinline__ void ldm_x4(uint32_t* r, uint32_t addr) {
    asm volatile("ldmatrix.sync.aligned.m8n8.x4.shared.b16 {%0,%1,%2,%3}, [%4];"
                 : "=r"(r[0]), "=r"(r[1]), "=r"(r[2]), "=r"(r[3]) : "r"(addr));
}
__device__ __forceinline__ void mma16816(float* c, const uint32_t* a, const uint32_t* b) {
    asm volatile("mma.sync.aligned.m16n8k16.row.col.f32.bf16.bf16.f32 "
                 "{%0,%1,%2,%3}, {%4,%5,%6,%7}, {%8,%9}, {%0,%1,%2,%3};"
                 : "+f"(c[0]), "+f"(c[1]), "+f"(c[2]), "+f"(c[3])
                 : "r"(a[0]), "r"(a[1]), "r"(a[2]), "r"(a[3]), "r"(b[0]), "r"(b[1]));
}
__device__ __forceinline__ float gelu_f(float x) {
    return 0.5f * x * (1.0f + erff(x * 0.7071067811865475f));
}

// ---------------- small kernels ----------------
__global__ void k_transpose(const float* __restrict__ x) {
    __shared__ float tile[32][33];
    int b = blockIdx.z, n0 = blockIdx.x * 32, c0 = blockIdx.y * 32;
    int tx = threadIdx.x, ty = threadIdx.y;
    const float* xb = x + (size_t)b * C_ * Nn;
#pragma unroll
    for (int i = 0; i < 4; i++)
        tile[ty + i * 8][tx] = xb[(size_t)(c0 + ty + i * 8) * Nn + n0 + tx];
    __syncthreads();
    float* xtb = g_xt + (size_t)b * Nn * C_;
#pragma unroll
    for (int i = 0; i < 4; i++)
        xtb[(size_t)(n0 + ty + i * 8) * C_ + c0 + tx] = tile[tx][ty + i * 8];
}

// gather + neighbor-diff max; interleaved channels, hi/lo bf16 split -> gA1 [M,768]
__global__ void k_feats(const int* __restrict__ edge) {
    __shared__ int sj[Kn], si[Kn];
    int n = blockIdx.x, b = blockIdx.y;
    int t = threadIdx.x;
    if (t < Kn)          sj[t]      = edge[((size_t)b * Nn + n) * Kn + t];
    else if (t < 2 * Kn) si[t - Kn] = edge[((size_t)(B_ + b) * Nn + n) * Kn + (t - Kn)];
    __syncthreads();
    const float* xb = g_xt + (size_t)b * Nn * C_;
    int c = t;
    float xv = xb[(size_t)n * C_ + c];
    float mx = -INFINITY;
#pragma unroll
    for (int k = 0; k < Kn; k++)
        mx = fmaxf(mx, xb[(size_t)sj[k] * C_ + c] - xb[(size_t)si[k] * C_ + c]);
    __nv_bfloat16* row = gA1 + (size_t)(b * Nn + n) * KSPLIT;
    __nv_bfloat16 xh = __float2bfloat16(xv);
    __nv_bfloat16 mh = __float2bfloat16(mx);
    row[2 * c]           = xh;
    row[2 * c + 1]       = mh;
    row[384 + 2 * c]     = __float2bfloat16(xv - __bfloat162float(xh));
    row[384 + 2 * c + 1] = __float2bfloat16(mx - __bfloat162float(mh));
}

// fp32 weights -> bf16 hi/lo split; also zeros stat accumulators
__global__ void k_wprep(const float* __restrict__ w1, const float* __restrict__ w2) {
    int i = blockIdx.x * 256 + threadIdx.x;
    if (i < C2_)  { g_sum1[i] = 0.f; g_sq1[i] = 0.f; }
    if (i < OUT_) { g_sum2[i] = 0.f; g_sq2[i] = 0.f; }
    if (i < C2_ * C2_) {
        int r = i / C2_, c = i % C2_;
        float v = w1[i];
        __nv_bfloat16 h = __float2bfloat16(v);
        gW1[(size_t)r * KSPLIT + c]       = h;
        gW1[(size_t)r * KSPLIT + 384 + c] = __float2bfloat16(v - __bfloat162float(h));
    } else if (i < C2_ * C2_ + OUT_ * C2_) {
        int j = i - C2_ * C2_;
        int r = j / C2_, c = j % C2_;
        float v = w2[j];
        __nv_bfloat16 h = __float2bfloat16(v);
        gW2[(size_t)r * KSPLIT + c]       = h;
        gW2[(size_t)r * KSPLIT + 384 + c] = __float2bfloat16(v - __bfloat162float(h));
    }
}

// ---------------- bf16 mma.sync GEMM with fused bias + BN stats ----------------
// BM=128, BK=64, 3-stage cp.async pipeline, 8 warps (2m x 4n), warp tile 64 x (BN/4).
// MINB = min blocks/SM for __launch_bounds__: GEMM1<128,2> (regs 128, 2 CTAs),
// GEMM2<64,3> (acc only 32 regs -> fits 85-reg cap, 3 CTAs, same BM/ldsm ratio).
#define BMg 128
#define MFRAG 4
#define STG 3

template <int BN, int MINB>
__global__ void __launch_bounds__(256, MINB) k_gemm_mma(
    const __nv_bfloat16* __restrict__ A, const __nv_bfloat16* __restrict__ W,
    const float* __restrict__ bias, float* __restrict__ Cout,
    float* __restrict__ sOut, float* __restrict__ qOut, int Nout)
{
    constexpr int WN = BN / 4;          // warp n-extent
    constexpr int NFRAG = WN / 8;       // n8 frags per warp
    constexpr int A_BYTES = BMg * 128;  // 128 rows x 64 bf16 = 16 KB
    constexpr int B_BYTES = BN * 128;
    constexpr int STAGE = A_BYTES + B_BYTES;

    extern __shared__ char sm[];
    __shared__ float redS[BN], redQ[BN];
    uint32_t sb = smem_u32(sm);

    int tid = threadIdx.x, lane = tid & 31, wid = tid >> 5;
    int wm = wid & 1, wn = wid >> 1;          // warps: 2 (m) x 4 (n)
    int mBase = blockIdx.y * BMg, nBase = blockIdx.x * BN;

    for (int j = tid; j < BN; j += 256) { redS[j] = 0.f; redQ[j] = 0.f; }

    float acc[MFRAG][NFRAG][4];
#pragma unroll
    for (int mi = 0; mi < MFRAG; mi++)
#pragma unroll
        for (int nf = 0; nf < NFRAG; nf++)
#pragma unroll
            for (int q = 0; q < 4; q++) acc[mi][nf][q] = 0.f;

    auto load_stage = [&](int t, int s) {
        int u = t % 6;
        int kA = (t < 6 || t >= 12) ? u * 64 : 384 + u * 64;
        int kW = (t < 12) ? u * 64 : 384 + u * 64;
        const char* Ag = (const char*)A + ((size_t)mBase * KSPLIT + kA) * 2;
        const char* Wg = (const char*)W + ((size_t)nBase * KSPLIT + kW) * 2;
        uint32_t as = sb + s * STAGE;
        uint32_t bs = as + A_BYTES;
#pragma unroll
        for (int i = 0; i < BMg * 8 / 256; i++) {      // A granules (1024/256 = 4)
            int gi = tid + i * 256;
            int r = gi >> 3, g = gi & 7;
            CP16(as + r * 128 + ((g ^ (r & 7)) << 4), Ag + (size_t)r * (KSPLIT * 2) + g * 16);
        }
#pragma unroll
        for (int i = 0; i < BN * 8 / 256; i++) {       // W granules
            int gi = tid + i * 256;
            int n = gi >> 3, g = gi & 7;
            CP16(bs + n * 128 + ((g ^ (n & 7)) << 4), Wg + (size_t)n * (KSPLIT * 2) + g * 16);
        }
        CP_COMMIT();
    };

    for (int t = 0; t < STG - 1; t++) load_stage(t, t);

    for (int t = 0; t < KCHUNKS; t++) {
        if (t + 1 < KCHUNKS) asm volatile("cp.async.wait_group 1;" ::: "memory");
        else                 asm volatile("cp.async.wait_group 0;" ::: "memory");
        __syncthreads();
        if (t + STG - 1 < KCHUNKS) load_stage(t + STG - 1, (t + STG - 1) % STG);

        uint32_t as = sb + (t % STG) * STAGE;
        uint32_t bsm = as + A_BYTES;
#pragma unroll
        for (int ks = 0; ks < 4; ks++) {
            uint32_t af[MFRAG][4];
#pragma unroll
            for (int mi = 0; mi < MFRAG; mi++) {
                int row = wm * 64 + mi * 16 + (lane & 15);
                int g = ks * 2 + (lane >> 4);
                ldm_x4(af[mi], as + row * 128 + ((g ^ (row & 7)) << 4));
            }
            uint32_t bf[NFRAG][2];
#pragma unroll
            for (int j2 = 0; j2 < NFRAG / 2; j2++) {
                int quad = lane >> 3;
                int n = wn * WN + j2 * 16 + (lane & 7) + (quad >> 1) * 8;
                int g = ks * 2 + (quad & 1);
                uint32_t r4[4];
                ldm_x4(r4, bsm + n * 128 + ((g ^ (n & 7)) << 4));
                bf[2 * j2][0] = r4[0]; bf[2 * j2][1] = r4[1];
                bf[2 * j2 + 1][0] = r4[2]; bf[2 * j2 + 1][1] = r4[3];
            }
#pragma unroll
            for (int mi = 0; mi < MFRAG; mi++)
#pragma unroll
                for (int nf = 0; nf < NFRAG; nf++)
                    mma16816(acc[mi][nf], af[mi], bf[nf]);
        }
    }

    // -------- epilogue: bias, store, fused per-channel sum/sumsq --------
    int g = lane >> 2, tig = lane & 3;
#pragma unroll
    for (int nf = 0; nf < NFRAG; nf++) {
        int colL = wn * WN + nf * 8 + 2 * tig;        // block-local column
        int col = nBase + colL;
        float b0 = bias[col], b1 = bias[col + 1];
        float s0 = 0.f, q0 = 0.f, s1 = 0.f, q1 = 0.f;
#pragma unroll
        for (int mi = 0; mi < MFRAG; mi++) {
            int row0 = mBase + wm * 64 + mi * 16 + g;
            float v0 = acc[mi][nf][0] + b0;
            float v1 = acc[mi][nf][1] + b1;
            float v2 = acc[mi][nf][2] + b0;
            float v3 = acc[mi][nf][3] + b1;
            *(float2*)(Cout + (size_t)row0 * Nout + col)       = make_float2(v0, v1);
            *(float2*)(Cout + (size_t)(row0 + 8) * Nout + col) = make_float2(v2, v3);
            s0 += v0 + v2; q0 += v0 * v0 + v2 * v2;
            s1 += v1 + v3; q1 += v1 * v1 + v3 * v3;
        }
#pragma unroll
        for (int o = 4; o <= 16; o <<= 1) {           // reduce over g (lane bits 2..4)
            s0 += __shfl_xor_sync(0xffffffffu, s0, o);
            q0 += __shfl_xor_sync(0xffffffffu, q0, o);
            s1 += __shfl_xor_sync(0xffffffffu, s1, o);
            q1 += __shfl_xor_sync(0xffffffffu, q1, o);
        }
        if (g == 0) {
            atomicAdd(&redS[colL], s0);     atomicAdd(&redQ[colL], q0);
            atomicAdd(&redS[colL + 1], s1); atomicAdd(&redQ[colL + 1], q1);
        }
    }
    __syncthreads();
    if (tid < BN) {
        atomicAdd(&sOut[nBase + tid], redS[tid]);
        atomicAdd(&qOut[nBase + tid], redQ[tid]);
    }
}

// ---------------- stats -> scale/shift ----------------
__global__ void k_fin(const float* __restrict__ sum, const float* __restrict__ sq,
                      const float* __restrict__ g, const float* __restrict__ beta,
                      float* __restrict__ scale, float* __restrict__ shift, int Cn)
{
    int c = threadIdx.x;
    if (c < Cn) {
        float mean = sum[c] * (1.0f / M_);
        float var  = sq[c] * (1.0f / M_) - mean * mean;
        float sc = g[c] * rsqrtf(var + EPS_);
        scale[c] = sc;
        shift[c] = beta[c] - mean * sc;
    }
}

// ---------------- BN1+GELU1, fp32 h1 -> bf16 hi/lo gA2 ----------------
__global__ void k_act() {
    int i = blockIdx.x * blockDim.x + threadIdx.x;   // float4 index over [M,384]
    float4 v = ((const float4*)g_h1)[i];
    int c = (i % 96) * 4;
    int m = i / 96;
    float o[4];
    o[0] = gelu_f(g_scale1[c + 0] * v.x + g_shift1[c + 0]);
    o[1] = gelu_f(g_scale1[c + 1] * v.y + g_shift1[c + 1]);
    o[2] = gelu_f(g_scale1[c + 2] * v.z + g_shift1[c + 2]);
    o[3] = gelu_f(g_scale1[c + 3] * v.w + g_shift1[c + 3]);
    __nv_bfloat16 h[4], l[4];
#pragma unroll
    for (int q = 0; q < 4; q++) {
        h[q] = __float2bfloat16(o[q]);
        l[q] = __float2bfloat16(o[q] - __bfloat162float(h[q]));
    }
    __nv_bfloat16* rowp = gA2 + (size_t)m * KSPLIT + c;
    *(__nv_bfloat162*)(rowp)           = *(__nv_bfloat162*)&h[0];
    *(__nv_bfloat162*)(rowp + 2)       = *(__nv_bfloat162*)&h[2];
    *(__nv_bfloat162*)(rowp + 384)     = *(__nv_bfloat162*)&l[0];
    *(__nv_bfloat162*)(rowp + 384 + 2) = *(__nv_bfloat162*)&l[2];
}

// ---------------- BN2+GELU2 + transpose -> NCHW ----------------
__global__ void k_out(float* __restrict__ out) {
    __shared__ float tile[32][33];
    int b = blockIdx.z, n0 = blockIdx.x * 32, o0 = blockIdx.y * 32;
    int tx = threadIdx.x, ty = threadIdx.y;
    const float* h2 = g_h2 + (size_t)b * Nn * OUT_;
#pragma unroll
    for (int i = 0; i < 4; i++) {
        int n = n0 + ty + i * 8;
        int o = o0 + tx;
        float v = h2[(size_t)n * OUT_ + o];
        tile[ty + i * 8][tx] = gelu_f(g_scale2[o] * v + g_shift2[o]);
    }
    __syncthreads();
    float* ob = out + (size_t)b * OUT_ * Nn;
#pragma unroll
    for (int i = 0; i < 4; i++)
        ob[(size_t)(o0 + ty + i * 8) * Nn + n0 + tx] = tile[tx][ty + i * 8];
}

// ---------------- launch ----------------
extern "C" void kernel_launch(void* const* d_in, const int* in_sizes, int n_in,
                              void* d_out, int out_size) {
    const float* x     = (const float*)d_in[0];
    const int*   edge  = (const int*)d_in[1];
    const float* w1    = (const float*)d_in[2];
    const float* b1    = (const float*)d_in[3];
    const float* g1    = (const float*)d_in[4];
    const float* beta1 = (const float*)d_in[5];
    const float* w2    = (const float*)d_in[6];
    const float* b2    = (const float*)d_in[7];
    const float* g2    = (const float*)d_in[8];
    const float* beta2 = (const float*)d_in[9];
    float* out = (float*)d_out;

    __nv_bfloat16 *pA1, *pA2, *pW1, *pW2;
    float *pH1, *pH2, *pS1, *pQ1, *pS2, *pQ2, *pSc1, *pSh1, *pSc2, *pSh2;
    cudaGetSymbolAddress((void**)&pA1, gA1);
    cudaGetSymbolAddress((void**)&pA2, gA2);
    cudaGetSymbolAddress((void**)&pW1, gW1);
    cudaGetSymbolAddress((void**)&pW2, gW2);
    cudaGetSymbolAddress((void**)&pH1, g_h1);
    cudaGetSymbolAddress((void**)&pH2, g_h2);
    cudaGetSymbolAddress((void**)&pS1, g_sum1);
    cudaGetSymbolAddress((void**)&pQ1, g_sq1);
    cudaGetSymbolAddress((void**)&pS2, g_sum2);
    cudaGetSymbolAddress((void**)&pQ2, g_sq2);
    cudaGetSymbolAddress((void**)&pSc1, g_scale1);
    cudaGetSymbolAddress((void**)&pSh1, g_shift1);
    cudaGetSymbolAddress((void**)&pSc2, g_scale2);
    cudaGetSymbolAddress((void**)&pSh2, g_shift2);

    const int SM1 = STG * (BMg * 128 + 128 * 128);   // 96 KB, 2 CTAs/SM (reg-bound)
    const int SM2 = STG * (BMg * 128 + 64 * 128);    // 72 KB, 3 CTAs/SM
    cudaFuncSetAttribute((k_gemm_mma<128, 2>), cudaFuncAttributeMaxDynamicSharedMemorySize, SM1);
    cudaFuncSetAttribute((k_gemm_mma<64, 3>),  cudaFuncAttributeMaxDynamicSharedMemorySize, SM2);

    k_transpose<<<dim3(Nn / 32, C_ / 32, B_), dim3(32, 8)>>>(x);
    k_feats<<<dim3(Nn, B_), C_>>>(edge);
    k_wprep<<<(C2_ * C2_ + OUT_ * C2_ + 255) / 256, 256>>>(w1, w2);

    k_gemm_mma<128, 2><<<dim3(C2_ / 128, M_ / BMg), 256, SM1>>>(pA1, pW1, b1, pH1, pS1, pQ1, C2_);
    k_fin<<<1, C2_>>>(pS1, pQ1, g1, beta1, pSc1, pSh1, C2_);
    k_act<<<(M_ * C2_ / 4) / 256, 256>>>();

    k_gemm_mma<64, 3><<<dim3(OUT_ / 64, M_ / BMg), 256, SM2>>>(pA2, pW2, b2, pH2, pS2, pQ2, OUT_);
    k_fin<<<1, OUT_>>>(pS2, pQ2, g2, beta2, pSc2, pSh2, OUT_);

    k_out<<<dim3(Nn / 32, OUT_ / 32, B_), dim3(32, 8)>>>(out);
}